// round 12
// baseline (speedup 1.0000x reference)
#include <cuda_runtime.h>
#include <math.h>

// ---------------- grid config ----------------
#define G 32
#define G3 (G * G * G)          // 32768 cells
#define ORG (-5.0f)
#define H 0.3125f
#define INVH 3.2f
#define MAXP 16384

// ---------------- device scratch ----------------
__device__ int    g_start[2][G3 + 1];
__device__ float4 g_pts[2][MAXP];   // grid-sorted points
__device__ int    g_orig[2][MAXP];  // original index of sorted point
__device__ float  g_dist[2][MAXP];  // nearest distance per ORIGINAL index

__device__ __forceinline__ int cellco(float x) {
    int c = (int)floorf((x - ORG) * INVH);
    return min(G - 1, max(0, c));
}
__device__ __forceinline__ unsigned redux_min_u32(unsigned v) {
    unsigned d;
    asm("redux.sync.min.u32 %0, %1, 0xFFFFFFFF;" : "=r"(d) : "r"(v));
    return d;
}

// ---------------- kernel 1: full build (hist + scan + scatter) in smem ----------------
// One block per direction. No global counters -> no cross-replay invariants.
#define BT 1024
#define BCH (G3 / BT)   // 32 cells per thread
__global__ void __launch_bounds__(BT, 1)
k_build(const float* __restrict__ tp, const float* __restrict__ pp, int N, int M) {
    extern __shared__ int sh[];       // [G3] counts->cursors, then [BT] scan aux
    int* scnt = sh;
    int* aux = sh + G3;
    const int d = blockIdx.x;
    const float* __restrict__ P = d ? pp : tp;
    const int n = d ? M : N;
    const int t = threadIdx.x;

    for (int c = t; c < G3; c += BT) scnt[c] = 0;
    __syncthreads();

    // histogram (smem atomics, spread addresses)
    for (int i = t; i < n; i += BT) {
        int cx = cellco(P[3 * i + 0]);
        int cy = cellco(P[3 * i + 1]);
        int cz = cellco(P[3 * i + 2]);
        atomicAdd(&scnt[(cz * G + cy) * G + cx], 1);
    }
    __syncthreads();

    // per-thread chunk sums + block inclusive scan
    const int base = t * BCH;
    int s = 0;
    #pragma unroll
    for (int k = 0; k < BCH; k++) s += scnt[base + k];
    aux[t] = s;
    __syncthreads();
    for (int off = 1; off < BT; off <<= 1) {
        int v = (t >= off) ? aux[t - off] : 0;
        __syncthreads();
        aux[t] += v;
        __syncthreads();
    }
    int run = aux[t] - s;   // exclusive base of this chunk
    #pragma unroll
    for (int k = 0; k < BCH; k++) {
        int c = base + k;
        int cnt = scnt[c];
        g_start[d][c] = run;
        scnt[c] = run;      // cell cursor for scatter
        run += cnt;
    }
    if (t == BT - 1) g_start[d][G3] = run;   // == n
    __syncthreads();

    // scatter into grid order
    for (int i = t; i < n; i += BT) {
        float x = P[3 * i + 0], y = P[3 * i + 1], z = P[3 * i + 2];
        int c = (cellco(z) * G + cellco(y)) * G + cellco(x);
        int slot = atomicAdd(&scnt[c], 1);
        g_pts[d][slot] = make_float4(x, y, z, 0.f);
        g_orig[d][slot] = i;
    }
}
#define BUILD_SMEM ((G3 + BT) * sizeof(int))

// ---------------- kernel 2: exact NN, warp per query ----------------
#define QW 8
__global__ void __launch_bounds__(QW * 32)
k_query(int N, int M, float* __restrict__ out) {
    const int wg = blockIdx.x * QW + (threadIdx.x >> 5);
    const int lane = threadIdx.x & 31;
    if (wg >= N + M) return;            // whole warp exits together
    const int d = (wg >= N) ? 1 : 0;
    const int j = d ? (wg - N) : wg;
    const int s = 1 - d;

    const float4 q = g_pts[d][j];       // sorted -> warp-coherent cells
    const int cx = cellco(q.x), cy = cellco(q.y), cz = cellco(q.z);

    // ---- fast path: ring-1 box (27 cells = 9 x-spans), spans loaded in parallel ----
    int s0 = 0, s1 = 0;
    if (lane < 9) {
        int dz = lane / 3 - 1, dy = lane % 3 - 1;
        int z = cz + dz, y = cy + dy;
        if (z >= 0 && z < G && y >= 0 && y < G) {
            int rowbase = (z * G + y) * G;
            int xlo = max(cx - 1, 0), xhi = min(cx + 1, G - 1);
            s0 = g_start[s][rowbase + xlo];
            s1 = g_start[s][rowbase + xhi + 1];
        }
    }
    float best = 3e38f;
    #pragma unroll
    for (int r = 0; r < 9; r++) {
        int u0 = __shfl_sync(0xFFFFFFFFu, s0, r);
        int u1 = __shfl_sync(0xFFFFFFFFu, s1, r);
        for (int i = u0 + lane; i < u1; i += 32) {
            float4 p = g_pts[s][i];
            float dx = q.x - p.x, dy = q.y - p.y, dz = q.z - p.z;
            best = fminf(best, fmaf(dx, dx, fmaf(dy, dy, dz * dz)));
        }
    }
    best = __uint_as_float(redux_min_u32(__float_as_uint(best)));

    // termination bound for k=1 (grid-edge faces unreachable -> inf)
    {
        float dbx = fminf((cx - 1 <= 0)     ? 3e38f : q.x - (ORG + (cx - 1) * H),
                          (cx + 1 >= G - 1) ? 3e38f : (ORG + (cx + 2) * H) - q.x);
        float dby = fminf((cy - 1 <= 0)     ? 3e38f : q.y - (ORG + (cy - 1) * H),
                          (cy + 1 >= G - 1) ? 3e38f : (ORG + (cy + 2) * H) - q.y);
        float dbz = fminf((cz - 1 <= 0)     ? 3e38f : q.z - (ORG + (cz - 1) * H),
                          (cz + 1 >= G - 1) ? 3e38f : (ORG + (cz + 2) * H) - q.z);
        float db = fminf(dbx, fminf(dby, dbz));
        if (best > db * db) {
            // ---- rare expansion: generic shell loop from k=2 ----
            for (int k = 2; k <= G; k++) {
                int zlo = max(cz - k, 0), zhi = min(cz + k, G - 1);
                int ylo = max(cy - k, 0), yhi = min(cy + k, G - 1);
                int xlo = max(cx - k, 0), xhi = min(cx + k, G - 1);
                for (int z = zlo; z <= zhi; z++) {
                    int adz = (z > cz) ? (z - cz) : (cz - z);
                    for (int y = ylo; y <= yhi; y++) {
                        int ady = (y > cy) ? (y - cy) : (cy - y);
                        int rowbase = (z * G + y) * G;
                        if (adz == k || ady == k) {
                            int u0 = g_start[s][rowbase + xlo];
                            int u1 = g_start[s][rowbase + xhi + 1];
                            for (int i = u0 + lane; i < u1; i += 32) {
                                float4 p = g_pts[s][i];
                                float dx = q.x - p.x, dy = q.y - p.y, dz = q.z - p.z;
                                best = fminf(best, fmaf(dx, dx, fmaf(dy, dy, dz * dz)));
                            }
                        } else {
                            int xa = cx - k;
                            if (xa >= 0) {
                                int u0 = g_start[s][rowbase + xa];
                                int u1 = g_start[s][rowbase + xa + 1];
                                for (int i = u0 + lane; i < u1; i += 32) {
                                    float4 p = g_pts[s][i];
                                    float dx = q.x - p.x, dy = q.y - p.y, dz = q.z - p.z;
                                    best = fminf(best, fmaf(dx, dx, fmaf(dy, dy, dz * dz)));
                                }
                            }
                            int xb = cx + k;
                            if (xb <= G - 1) {
                                int u0 = g_start[s][rowbase + xb];
                                int u1 = g_start[s][rowbase + xb + 1];
                                for (int i = u0 + lane; i < u1; i += 32) {
                                    float4 p = g_pts[s][i];
                                    float dx = q.x - p.x, dy = q.y - p.y, dz = q.z - p.z;
                                    best = fminf(best, fmaf(dx, dx, fmaf(dy, dy, dz * dz)));
                                }
                            }
                        }
                    }
                }
                best = __uint_as_float(redux_min_u32(__float_as_uint(best)));

                bool coverall = (cx - k <= 0) && (cx + k >= G - 1) &&
                                (cy - k <= 0) && (cy + k >= G - 1) &&
                                (cz - k <= 0) && (cz + k >= G - 1);
                if (coverall) break;
                float ex = fminf((cx - k <= 0)     ? 3e38f : q.x - (ORG + (cx - k) * H),
                                 (cx + k >= G - 1) ? 3e38f : (ORG + (cx + k + 1) * H) - q.x);
                float ey = fminf((cy - k <= 0)     ? 3e38f : q.y - (ORG + (cy - k) * H),
                                 (cy + k >= G - 1) ? 3e38f : (ORG + (cy + k + 1) * H) - q.y);
                float ez = fminf((cz - k <= 0)     ? 3e38f : q.z - (ORG + (cz - k) * H),
                                 (cz + k >= G - 1) ? 3e38f : (ORG + (cz + k + 1) * H) - q.z);
                float eb = fminf(ex, fminf(ey, ez));
                if (best <= eb * eb) break;
            }
        }
    }

    if (lane == 0) {
        int orig = g_orig[d][j];
        float dist = sqrtf(best);
        g_dist[d][orig] = dist;
        if (d == 1) out[1 + orig] = dist;   // mins_seeds
    }
}

// ---------------- kernel 3: deterministic final sums + scalars ----------------
__global__ void k_out(int N, int M, float* __restrict__ out) {
    __shared__ float sm0[1024], sm1[1024];
    int t = threadIdx.x;
    float s0 = 0.f, s1 = 0.f;
    for (int i = t; i < N; i += 1024) s0 += g_dist[0][i];
    for (int i = t; i < M; i += 1024) s1 += g_dist[1][i];
    sm0[t] = s0; sm1[t] = s1;
    __syncthreads();
    for (int st = 512; st > 0; st >>= 1) {
        if (t < st) { sm0[t] += sm0[t + st]; sm1[t] += sm1[t + st]; }
        __syncthreads();
    }
    if (t == 0) {
        float loss = sm0[0] / (float)N;        // mean(mins)
        float loss_seeds = sm1[0] / (float)M;  // mean(mins_seeds)
        out[0] = loss + loss_seeds;
        out[1 + M] = loss;
        out[2 + M] = loss_seeds;
    }
}

// ---------------- launch ----------------
extern "C" void kernel_launch(void* const* d_in, const int* in_sizes, int n_in,
                              void* d_out, int out_size) {
    const float* tp = (const float*)d_in[0];
    const float* pp = (const float*)d_in[1];
    float* out = (float*)d_out;
    const int N = in_sizes[0] / 3;
    const int M = in_sizes[1] / 3;

    // allow >48KB dynamic smem (idempotent; not a stream op, capture-safe)
    cudaFuncSetAttribute(k_build, cudaFuncAttributeMaxDynamicSharedMemorySize,
                         (int)BUILD_SMEM);

    k_build<<<2, BT, BUILD_SMEM>>>(tp, pp, N, M);

    const int totalq = N + M;
    k_query<<<(totalq + QW - 1) / QW, QW * 32>>>(N, M, out);

    k_out<<<1, 1024>>>(N, M, out);
}

// round 13
// speedup vs baseline: 1.4241x; 1.4241x over previous
#include <cuda_runtime.h>
#include <math.h>

// ---------------- grid config ----------------
#define G 32
#define G3 (G * G * G)          // 32768 cells
#define ORG (-5.0f)
#define H 0.3125f
#define INVH 3.2f
#define MAXP 16384
#define NSB 32                  // scan blocks per direction (G3 / 1024)

// ---------------- device scratch ----------------
// g_cnt zero at entry: zero-initialized at load; k_scan3 re-zeroes each call.
__device__ int    g_cnt[2][G3];
__device__ int    g_incl[2][G3];     // per-1024-block inclusive scans
__device__ int    g_btot[2][NSB];    // block totals
__device__ int    g_start[2][G3 + 1];
__device__ int    g_cur[2][G3];
__device__ float4 g_pts[2][MAXP];    // grid-sorted points
__device__ int    g_orig[2][MAXP];   // original index of sorted point
__device__ float  g_dist[2][MAXP];   // nearest distance per ORIGINAL index

__device__ __forceinline__ int cellco(float x) {
    int c = (int)floorf((x - ORG) * INVH);
    return min(G - 1, max(0, c));
}
__device__ __forceinline__ unsigned redux_min_u32(unsigned v) {
    unsigned d;
    asm("redux.sync.min.u32 %0, %1, 0xFFFFFFFF;" : "=r"(d) : "r"(v));
    return d;
}

// ---------------- kernel 1: histogram (wide, global atomics) ----------------
__global__ void k_hist(const float* __restrict__ tp, const float* __restrict__ pp,
                       int N, int M) {
    int d = blockIdx.y;
    const float* __restrict__ P = d ? pp : tp;
    int n = d ? M : N;
    int i = blockIdx.x * 256 + threadIdx.x;
    if (i < n) {
        int cx = cellco(P[3 * i + 0]);
        int cy = cellco(P[3 * i + 1]);
        int cz = cellco(P[3 * i + 2]);
        atomicAdd(&g_cnt[d][(cz * G + cy) * G + cx], 1);
    }
}

// ---------------- kernel 2: per-block inclusive scan (coalesced) ----------------
__global__ void __launch_bounds__(1024) k_scan1() {
    __shared__ int sm[1024];
    int d = blockIdx.y;
    int c = blockIdx.x * 1024 + threadIdx.x;
    int t = threadIdx.x;
    int v = g_cnt[d][c];
    sm[t] = v;
    __syncthreads();
    #pragma unroll
    for (int off = 1; off < 1024; off <<= 1) {
        int u = (t >= off) ? sm[t - off] : 0;
        __syncthreads();
        sm[t] += u;
        __syncthreads();
    }
    g_incl[d][c] = sm[t];
    if (t == 1023) g_btot[d][blockIdx.x] = sm[t];
}

// ---------------- kernel 3: apply block offsets, build start/cur, re-zero cnt ----------------
__global__ void __launch_bounds__(1024) k_scan3(int N, int M) {
    int d = blockIdx.y;
    int b = blockIdx.x;
    int c = b * 1024 + threadIdx.x;
    int boff = 0;
    for (int k = 0; k < b; k++) boff += g_btot[d][k];   // <=31 adds, L2-hot
    int incl = g_incl[d][c] + boff;
    int excl = incl - g_cnt[d][c];
    g_start[d][c] = excl;
    g_cur[d][c] = excl;
    g_cnt[d][c] = 0;                                    // restore entry invariant
    if (c == G3 - 1) g_start[d][G3] = d ? M : N;
}

// ---------------- kernel 4: scatter into grid order ----------------
__global__ void k_scatter(const float* __restrict__ tp, const float* __restrict__ pp,
                          int N, int M) {
    int d = blockIdx.y;
    const float* __restrict__ P = d ? pp : tp;
    int n = d ? M : N;
    int i = blockIdx.x * 256 + threadIdx.x;
    if (i < n) {
        float x = P[3 * i + 0], y = P[3 * i + 1], z = P[3 * i + 2];
        int c = (cellco(z) * G + cellco(y)) * G + cellco(x);
        int slot = atomicAdd(&g_cur[d][c], 1);
        g_pts[d][slot] = make_float4(x, y, z, 0.f);
        g_orig[d][slot] = i;
    }
}

// ---------------- kernel 5: exact NN, warp per query ----------------
#define QW 8
__global__ void __launch_bounds__(QW * 32)
k_query(int N, int M, float* __restrict__ out) {
    const int wg = blockIdx.x * QW + (threadIdx.x >> 5);
    const int lane = threadIdx.x & 31;
    if (wg >= N + M) return;            // whole warp exits together
    const int d = (wg >= N) ? 1 : 0;
    const int j = d ? (wg - N) : wg;
    const int s = 1 - d;

    const float4 q = g_pts[d][j];       // sorted -> warp-coherent cells
    const int cx = cellco(q.x), cy = cellco(q.y), cz = cellco(q.z);

    // ---- fast path: ring-1 box (27 cells = 9 x-spans), spans loaded in parallel ----
    int s0 = 0, s1 = 0;
    if (lane < 9) {
        int dz = lane / 3 - 1, dy = lane % 3 - 1;
        int z = cz + dz, y = cy + dy;
        if (z >= 0 && z < G && y >= 0 && y < G) {
            int rowbase = (z * G + y) * G;
            int xlo = max(cx - 1, 0), xhi = min(cx + 1, G - 1);
            s0 = g_start[s][rowbase + xlo];
            s1 = g_start[s][rowbase + xhi + 1];
        }
    }
    float best = 3e38f;
    #pragma unroll
    for (int r = 0; r < 9; r++) {
        int u0 = __shfl_sync(0xFFFFFFFFu, s0, r);
        int u1 = __shfl_sync(0xFFFFFFFFu, s1, r);
        for (int i = u0 + lane; i < u1; i += 32) {
            float4 p = g_pts[s][i];
            float dx = q.x - p.x, dy = q.y - p.y, dz = q.z - p.z;
            best = fminf(best, fmaf(dx, dx, fmaf(dy, dy, dz * dz)));
        }
    }
    best = __uint_as_float(redux_min_u32(__float_as_uint(best)));

    // termination bound for k=1 (grid-edge faces unreachable -> inf)
    {
        float dbx = fminf((cx - 1 <= 0)     ? 3e38f : q.x - (ORG + (cx - 1) * H),
                          (cx + 1 >= G - 1) ? 3e38f : (ORG + (cx + 2) * H) - q.x);
        float dby = fminf((cy - 1 <= 0)     ? 3e38f : q.y - (ORG + (cy - 1) * H),
                          (cy + 1 >= G - 1) ? 3e38f : (ORG + (cy + 2) * H) - q.y);
        float dbz = fminf((cz - 1 <= 0)     ? 3e38f : q.z - (ORG + (cz - 1) * H),
                          (cz + 1 >= G - 1) ? 3e38f : (ORG + (cz + 2) * H) - q.z);
        float db = fminf(dbx, fminf(dby, dbz));
        if (best > db * db) {
            // ---- rare expansion: generic shell loop from k=2 ----
            for (int k = 2; k <= G; k++) {
                int zlo = max(cz - k, 0), zhi = min(cz + k, G - 1);
                int ylo = max(cy - k, 0), yhi = min(cy + k, G - 1);
                int xlo = max(cx - k, 0), xhi = min(cx + k, G - 1);
                for (int z = zlo; z <= zhi; z++) {
                    int adz = (z > cz) ? (z - cz) : (cz - z);
                    for (int y = ylo; y <= yhi; y++) {
                        int ady = (y > cy) ? (y - cy) : (cy - y);
                        int rowbase = (z * G + y) * G;
                        if (adz == k || ady == k) {
                            int u0 = g_start[s][rowbase + xlo];
                            int u1 = g_start[s][rowbase + xhi + 1];
                            for (int i = u0 + lane; i < u1; i += 32) {
                                float4 p = g_pts[s][i];
                                float dx = q.x - p.x, dy = q.y - p.y, dz = q.z - p.z;
                                best = fminf(best, fmaf(dx, dx, fmaf(dy, dy, dz * dz)));
                            }
                        } else {
                            int xa = cx - k;
                            if (xa >= 0) {
                                int u0 = g_start[s][rowbase + xa];
                                int u1 = g_start[s][rowbase + xa + 1];
                                for (int i = u0 + lane; i < u1; i += 32) {
                                    float4 p = g_pts[s][i];
                                    float dx = q.x - p.x, dy = q.y - p.y, dz = q.z - p.z;
                                    best = fminf(best, fmaf(dx, dx, fmaf(dy, dy, dz * dz)));
                                }
                            }
                            int xb = cx + k;
                            if (xb <= G - 1) {
                                int u0 = g_start[s][rowbase + xb];
                                int u1 = g_start[s][rowbase + xb + 1];
                                for (int i = u0 + lane; i < u1; i += 32) {
                                    float4 p = g_pts[s][i];
                                    float dx = q.x - p.x, dy = q.y - p.y, dz = q.z - p.z;
                                    best = fminf(best, fmaf(dx, dx, fmaf(dy, dy, dz * dz)));
                                }
                            }
                        }
                    }
                }
                best = __uint_as_float(redux_min_u32(__float_as_uint(best)));

                bool coverall = (cx - k <= 0) && (cx + k >= G - 1) &&
                                (cy - k <= 0) && (cy + k >= G - 1) &&
                                (cz - k <= 0) && (cz + k >= G - 1);
                if (coverall) break;
                float ex = fminf((cx - k <= 0)     ? 3e38f : q.x - (ORG + (cx - k) * H),
                                 (cx + k >= G - 1) ? 3e38f : (ORG + (cx + k + 1) * H) - q.x);
                float ey = fminf((cy - k <= 0)     ? 3e38f : q.y - (ORG + (cy - k) * H),
                                 (cy + k >= G - 1) ? 3e38f : (ORG + (cy + k + 1) * H) - q.y);
                float ez = fminf((cz - k <= 0)     ? 3e38f : q.z - (ORG + (cz - k) * H),
                                 (cz + k >= G - 1) ? 3e38f : (ORG + (cz + k + 1) * H) - q.z);
                float eb = fminf(ex, fminf(ey, ez));
                if (best <= eb * eb) break;
            }
        }
    }

    if (lane == 0) {
        int orig = g_orig[d][j];
        float dist = sqrtf(best);
        g_dist[d][orig] = dist;
        if (d == 1) out[1 + orig] = dist;   // mins_seeds
    }
}

// ---------------- kernel 6: deterministic final sums + scalars ----------------
__global__ void k_out(int N, int M, float* __restrict__ out) {
    __shared__ float sm0[1024], sm1[1024];
    int t = threadIdx.x;
    float s0 = 0.f, s1 = 0.f;
    for (int i = t; i < N; i += 1024) s0 += g_dist[0][i];
    for (int i = t; i < M; i += 1024) s1 += g_dist[1][i];
    sm0[t] = s0; sm1[t] = s1;
    __syncthreads();
    for (int st = 512; st > 0; st >>= 1) {
        if (t < st) { sm0[t] += sm0[t + st]; sm1[t] += sm1[t + st]; }
        __syncthreads();
    }
    if (t == 0) {
        float loss = sm0[0] / (float)N;        // mean(mins)
        float loss_seeds = sm1[0] / (float)M;  // mean(mins_seeds)
        out[0] = loss + loss_seeds;
        out[1 + M] = loss;
        out[2 + M] = loss_seeds;
    }
}

// ---------------- launch ----------------
extern "C" void kernel_launch(void* const* d_in, const int* in_sizes, int n_in,
                              void* d_out, int out_size) {
    const float* tp = (const float*)d_in[0];
    const float* pp = (const float*)d_in[1];
    float* out = (float*)d_out;
    const int N = in_sizes[0] / 3;
    const int M = in_sizes[1] / 3;
    const int maxP = (N > M) ? N : M;

    dim3 gp((maxP + 255) / 256, 2);
    k_hist<<<gp, 256>>>(tp, pp, N, M);

    dim3 gs(NSB, 2);
    k_scan1<<<gs, 1024>>>();
    k_scan3<<<gs, 1024>>>(N, M);

    k_scatter<<<gp, 256>>>(tp, pp, N, M);

    const int totalq = N + M;
    k_query<<<(totalq + QW - 1) / QW, QW * 32>>>(N, M, out);

    k_out<<<1, 1024>>>(N, M, out);
}

// round 14
// speedup vs baseline: 2.3750x; 1.6677x over previous
#include <cuda_runtime.h>
#include <math.h>

// ---------------- grid config ----------------
#define G 20
#define G3 (G * G * G)          // 8000 cells
#define ORG (-5.0f)
#define H 0.5f
#define INVH 2.0f
#define MAXP 16384

// ---------------- device scratch ----------------
// g_cnt zero at entry: zero-initialized at load; k_scatter re-zeroes each call.
__device__ int    g_cnt[2][G3];
__device__ int    g_start[2][G3 + 1];
__device__ int    g_cur[2][G3];
__device__ float4 g_pts[2][MAXP];   // grid-sorted points
__device__ int    g_orig[2][MAXP];  // original index of sorted point
__device__ float  g_dist[2][MAXP];  // nearest distance per ORIGINAL index

__device__ __forceinline__ int cellco(float x) {
    int c = (int)floorf((x - ORG) * INVH);
    return min(G - 1, max(0, c));
}
__device__ __forceinline__ unsigned redux_min_u32(unsigned v) {
    unsigned d;
    asm("redux.sync.min.u32 %0, %1, 0xFFFFFFFF;" : "=r"(d) : "r"(v));
    return d;
}

// ---------------- kernel 1: histogram ----------------
__global__ void k_hist(const float* __restrict__ tp, const float* __restrict__ pp,
                       int N, int M) {
    int d = blockIdx.y;
    const float* __restrict__ P = d ? pp : tp;
    int n = d ? M : N;
    int i = blockIdx.x * 256 + threadIdx.x;
    if (i < n) {
        int cx = cellco(P[3 * i + 0]);
        int cy = cellco(P[3 * i + 1]);
        int cz = cellco(P[3 * i + 2]);
        atomicAdd(&g_cnt[d][(cz * G + cy) * G + cx], 1);
    }
}

// ---------------- kernel 2: exclusive prefix sum (one block per dir) ----------------
#define SCAN_T 1024
#define CH 8   // 1024*8 = 8192 >= 8000
__global__ void __launch_bounds__(SCAN_T) k_scan(int N, int M) {
    __shared__ int sm[SCAN_T];
    int d = blockIdx.x;
    int t = threadIdx.x;
    int base = t * CH;
    int s = 0;
    #pragma unroll
    for (int i = 0; i < CH; i++) {
        int c = base + i;
        if (c < G3) s += g_cnt[d][c];
    }
    sm[t] = s;
    __syncthreads();
    for (int off = 1; off < SCAN_T; off <<= 1) {
        int v = (t >= off) ? sm[t - off] : 0;
        __syncthreads();
        sm[t] += v;
        __syncthreads();
    }
    int run = sm[t] - s;  // exclusive base for this chunk
    #pragma unroll
    for (int i = 0; i < CH; i++) {
        int c = base + i;
        if (c < G3) {
            int cnt = g_cnt[d][c];
            g_start[d][c] = run;
            g_cur[d][c] = run;
            run += cnt;
        }
    }
    if (t == SCAN_T - 1) g_start[d][G3] = d ? M : N;
}

// ---------------- kernel 3: scatter into grid order + re-zero counts ----------------
__global__ void k_scatter(const float* __restrict__ tp, const float* __restrict__ pp,
                          int N, int M) {
    int d = blockIdx.y;
    const float* __restrict__ P = d ? pp : tp;
    int n = d ? M : N;
    int i = blockIdx.x * 256 + threadIdx.x;
    if (i < n) {
        float x = P[3 * i + 0], y = P[3 * i + 1], z = P[3 * i + 2];
        int c = (cellco(z) * G + cellco(y)) * G + cellco(x);
        int slot = atomicAdd(&g_cur[d][c], 1);
        g_pts[d][slot] = make_float4(x, y, z, 0.f);
        g_orig[d][slot] = i;
    }
    // re-zero counts for the next graph replay
    int nthread = gridDim.x * 256;
    for (int c = blockIdx.x * 256 + threadIdx.x; c < G3; c += nthread)
        g_cnt[d][c] = 0;
}

// ---------------- kernel 4: exact NN, warp per query, parallel spans ----------------
#define QW 8
__global__ void __launch_bounds__(QW * 32)
k_query(int N, int M, float* __restrict__ out) {
    const int wg = blockIdx.x * QW + (threadIdx.x >> 5);
    const int lane = threadIdx.x & 31;
    if (wg >= N + M) return;            // whole warp exits together
    const int d = (wg >= N) ? 1 : 0;
    const int j = d ? (wg - N) : wg;
    const int s = 1 - d;

    const float4 q = g_pts[d][j];       // sorted -> warp-coherent cells
    const int cx = cellco(q.x), cy = cellco(q.y), cz = cellco(q.z);

    // ---- fast path: ring-1 box (27 cells = 9 x-spans), spans loaded in parallel ----
    int s0 = 0, s1 = 0;
    if (lane < 9) {
        int dz = lane / 3 - 1, dy = lane % 3 - 1;
        int z = cz + dz, y = cy + dy;
        if (z >= 0 && z < G && y >= 0 && y < G) {
            int rowbase = (z * G + y) * G;
            int xlo = max(cx - 1, 0), xhi = min(cx + 1, G - 1);
            s0 = g_start[s][rowbase + xlo];
            s1 = g_start[s][rowbase + xhi + 1];
        }
    }
    float best = 3e38f;
    #pragma unroll
    for (int r = 0; r < 9; r++) {
        int u0 = __shfl_sync(0xFFFFFFFFu, s0, r);
        int u1 = __shfl_sync(0xFFFFFFFFu, s1, r);
        for (int i = u0 + lane; i < u1; i += 32) {
            float4 p = g_pts[s][i];
            float dx = q.x - p.x, dy = q.y - p.y, dz = q.z - p.z;
            best = fminf(best, fmaf(dx, dx, fmaf(dy, dy, dz * dz)));
        }
    }
    best = __uint_as_float(redux_min_u32(__float_as_uint(best)));

    // termination bound for k=1 (unsearched region beyond searched box faces)
    float dbx = fminf((cx - 1 <= 0)     ? 3e38f : q.x - (ORG + (cx - 1) * H),
                      (cx + 1 >= G - 1) ? 3e38f : (ORG + (cx + 2) * H) - q.x);
    float dby = fminf((cy - 1 <= 0)     ? 3e38f : q.y - (ORG + (cy - 1) * H),
                      (cy + 1 >= G - 1) ? 3e38f : (ORG + (cy + 2) * H) - q.y);
    float dbz = fminf((cz - 1 <= 0)     ? 3e38f : q.z - (ORG + (cz - 1) * H),
                      (cz + 1 >= G - 1) ? 3e38f : (ORG + (cz + 2) * H) - q.z);
    float db = fminf(dbx, fminf(dby, dbz));

    if (best > db * db) {
        // ---- rare expansion: rescan full box per k, rows batched across lanes ----
        for (int k = 2; k <= G; k++) {
            int zlo = max(cz - k, 0), zhi = min(cz + k, G - 1);
            int ylo = max(cy - k, 0), yhi = min(cy + k, G - 1);
            int xlo = max(cx - k, 0), xhi = min(cx + k, G - 1);
            int ydim = yhi - ylo + 1;
            int R = (zhi - zlo + 1) * ydim;
            for (int rb = 0; rb < R; rb += 32) {
                int r = rb + lane;
                int u0 = 0, u1 = 0;
                if (r < R) {
                    int z = zlo + r / ydim;
                    int y = ylo + r % ydim;
                    int rowbase = (z * G + y) * G;
                    u0 = g_start[s][rowbase + xlo];
                    u1 = g_start[s][rowbase + xhi + 1];
                }
                int cnt = min(32, R - rb);
                for (int rr = 0; rr < cnt; rr++) {
                    int v0 = __shfl_sync(0xFFFFFFFFu, u0, rr);
                    int v1 = __shfl_sync(0xFFFFFFFFu, u1, rr);
                    for (int i = v0 + lane; i < v1; i += 32) {
                        float4 p = g_pts[s][i];
                        float dx = q.x - p.x, dy = q.y - p.y, dz = q.z - p.z;
                        best = fminf(best, fmaf(dx, dx, fmaf(dy, dy, dz * dz)));
                    }
                }
            }
            best = __uint_as_float(redux_min_u32(__float_as_uint(best)));

            bool coverall = (cx - k <= 0) && (cx + k >= G - 1) &&
                            (cy - k <= 0) && (cy + k >= G - 1) &&
                            (cz - k <= 0) && (cz + k >= G - 1);
            if (coverall) break;
            float ex = fminf((cx - k <= 0)     ? 3e38f : q.x - (ORG + (cx - k) * H),
                             (cx + k >= G - 1) ? 3e38f : (ORG + (cx + k + 1) * H) - q.x);
            float ey = fminf((cy - k <= 0)     ? 3e38f : q.y - (ORG + (cy - k) * H),
                             (cy + k >= G - 1) ? 3e38f : (ORG + (cy + k + 1) * H) - q.y);
            float ez = fminf((cz - k <= 0)     ? 3e38f : q.z - (ORG + (cz - k) * H),
                             (cz + k >= G - 1) ? 3e38f : (ORG + (cz + k + 1) * H) - q.z);
            float eb = fminf(ex, fminf(ey, ez));
            if (best <= eb * eb) break;
        }
    }

    if (lane == 0) {
        int orig = g_orig[d][j];
        float dist = sqrtf(best);
        g_dist[d][orig] = dist;
        if (d == 1) out[1 + orig] = dist;   // mins_seeds
    }
}

// ---------------- kernel 5: deterministic final sums + scalars ----------------
__global__ void k_out(int N, int M, float* __restrict__ out) {
    __shared__ float sm0[1024], sm1[1024];
    int t = threadIdx.x;
    float s0 = 0.f, s1 = 0.f;
    for (int i = t; i < N; i += 1024) s0 += g_dist[0][i];
    for (int i = t; i < M; i += 1024) s1 += g_dist[1][i];
    sm0[t] = s0; sm1[t] = s1;
    __syncthreads();
    for (int st = 512; st > 0; st >>= 1) {
        if (t < st) { sm0[t] += sm0[t + st]; sm1[t] += sm1[t + st]; }
        __syncthreads();
    }
    if (t == 0) {
        float loss = sm0[0] / (float)N;        // mean(mins)
        float loss_seeds = sm1[0] / (float)M;  // mean(mins_seeds)
        out[0] = loss + loss_seeds;
        out[1 + M] = loss;
        out[2 + M] = loss_seeds;
    }
}

// ---------------- launch ----------------
extern "C" void kernel_launch(void* const* d_in, const int* in_sizes, int n_in,
                              void* d_out, int out_size) {
    const float* tp = (const float*)d_in[0];
    const float* pp = (const float*)d_in[1];
    float* out = (float*)d_out;
    const int N = in_sizes[0] / 3;
    const int M = in_sizes[1] / 3;
    const int maxP = (N > M) ? N : M;

    dim3 gp((maxP + 255) / 256, 2);
    k_hist<<<gp, 256>>>(tp, pp, N, M);

    k_scan<<<2, SCAN_T>>>(N, M);

    k_scatter<<<gp, 256>>>(tp, pp, N, M);

    const int totalq = N + M;
    k_query<<<(totalq + QW - 1) / QW, QW * 32>>>(N, M, out);

    k_out<<<1, 1024>>>(N, M, out);
}